// round 2
// baseline (speedup 1.0000x reference)
#include <cuda_runtime.h>
#include <cuda_bf16.h>
#include <stdint.h>

// Problem constants
#define NN 8192
#define MM 8192
#define DD 64
#define TILE 128
#define NTILE (NN / TILE)   // 64

// ---------------- device scratch (no allocations allowed) ----------------
__device__ float g_xsq[NN];
__device__ float g_ysq[MM];
__device__ float g_rowsum[NN];
__device__ float g_colsum[MM];
__device__ unsigned long long g_rowmaxp[NN];
__device__ unsigned long long g_colmaxp[MM];
__device__ float g_lp_rows[NN];
__device__ float g_lp_cols[MM];
__device__ int   g_choice_rows[NN];
__device__ int   g_choice_cols[MM];

// Orderable key for float: larger float -> larger uint
__device__ __forceinline__ unsigned fkey(float f) {
    unsigned u = __float_as_uint(f);
    return u ^ ((unsigned)(((int)u) >> 31) | 0x80000000u);
}
__device__ __forceinline__ float unfkey(unsigned k) {
    unsigned u = (k & 0x80000000u) ? (k ^ 0x80000000u) : ~k;
    return __uint_as_float(u);
}

// ---------------- init ----------------
__global__ void init_kernel() {
    int t = blockIdx.x * blockDim.x + threadIdx.x;
    if (t < NN) {
        g_rowsum[t] = 0.f;
        g_colsum[t] = 0.f;
        g_rowmaxp[t] = 0ull;
        g_colmaxp[t] = 0ull;
    }
}

// ---------------- squared norms ----------------
__global__ void sqnorm_kernel(const float* __restrict__ x,
                              const float* __restrict__ y) {
    int t = blockIdx.x * blockDim.x + threadIdx.x;
    if (t >= 2 * NN) return;
    const float* base = (t < NN) ? (x + (size_t)t * DD)
                                 : (y + (size_t)(t - NN) * DD);
    float s = 0.f;
#pragma unroll
    for (int k = 0; k < DD / 4; ++k) {
        float4 v = *(const float4*)(base + 4 * k);
        s += v.x * v.x + v.y * v.y + v.z * v.z + v.w * v.w;
    }
    if (t < NN) g_xsq[t] = s; else g_ysq[t - NN] = s;
}

// ---------------- main fused distance + softmax-stats kernel ----------------
// Tile 128x128, 256 threads, 8x8 per-thread microtile, K=64 in one shot.
// Dynamic smem layout:
//   float xT[64][132]  (x tile transposed, padded)
//   float yT[64][132]
//   float sxq[128], syq[128]
//   float scsum[128]; unsigned long long scmax[128]
#define XT_STRIDE 132
#define SMEM_XT 0
#define SMEM_YT (SMEM_XT + 64 * XT_STRIDE * 4)
#define SMEM_SXQ (SMEM_YT + 64 * XT_STRIDE * 4)
#define SMEM_SYQ (SMEM_SXQ + 128 * 4)
#define SMEM_CSUM (SMEM_SYQ + 128 * 4)
#define SMEM_CMAX ((SMEM_CSUM + 128 * 4 + 15) & ~15)
#define SMEM_TOTAL (SMEM_CMAX + 128 * 8)

__global__ void __launch_bounds__(256, 2)
matcher_main_kernel(const float* __restrict__ x, const float* __restrict__ y) {
    extern __shared__ char smem[];
    float* xT = (float*)(smem + SMEM_XT);
    float* yT = (float*)(smem + SMEM_YT);
    float* sxq = (float*)(smem + SMEM_SXQ);
    float* syq = (float*)(smem + SMEM_SYQ);
    float* scsum = (float*)(smem + SMEM_CSUM);
    unsigned long long* scmax = (unsigned long long*)(smem + SMEM_CMAX);

    const int tid = threadIdx.x;
    const int tx = tid & 15;          // 0..15 -> column group
    const int ty = tid >> 4;          // 0..15 -> row group
    const int i0 = ty * 8;
    const int j0 = tx * 8;
    const int ibase = blockIdx.y * TILE;
    const int jbase = blockIdx.x * TILE;

    // load tiles, transposed into smem
#pragma unroll
    for (int k = tid; k < TILE * (DD / 4); k += 256) {  // 2048 float4
        int r = k >> 4;
        int c4 = k & 15;
        float4 vx = *(const float4*)(x + (size_t)(ibase + r) * DD + c4 * 4);
        float4 vy = *(const float4*)(y + (size_t)(jbase + r) * DD + c4 * 4);
        int d = c4 * 4;
        xT[(d + 0) * XT_STRIDE + r] = vx.x;
        xT[(d + 1) * XT_STRIDE + r] = vx.y;
        xT[(d + 2) * XT_STRIDE + r] = vx.z;
        xT[(d + 3) * XT_STRIDE + r] = vx.w;
        yT[(d + 0) * XT_STRIDE + r] = vy.x;
        yT[(d + 1) * XT_STRIDE + r] = vy.y;
        yT[(d + 2) * XT_STRIDE + r] = vy.z;
        yT[(d + 3) * XT_STRIDE + r] = vy.w;
    }
    if (tid < 128) sxq[tid] = g_xsq[ibase + tid];
    else           syq[tid - 128] = g_ysq[jbase + tid - 128];
    __syncthreads();

    float acc[8][8];
#pragma unroll
    for (int r = 0; r < 8; ++r)
#pragma unroll
        for (int c = 0; c < 8; ++c) acc[r][c] = 0.f;

#pragma unroll 8
    for (int d = 0; d < DD; ++d) {
        float a[8], b[8];
        float4 t0 = *(const float4*)&xT[d * XT_STRIDE + i0];
        float4 t1 = *(const float4*)&xT[d * XT_STRIDE + i0 + 4];
        float4 u0 = *(const float4*)&yT[d * XT_STRIDE + j0];
        float4 u1 = *(const float4*)&yT[d * XT_STRIDE + j0 + 4];
        a[0]=t0.x; a[1]=t0.y; a[2]=t0.z; a[3]=t0.w;
        a[4]=t1.x; a[5]=t1.y; a[6]=t1.z; a[7]=t1.w;
        b[0]=u0.x; b[1]=u0.y; b[2]=u0.z; b[3]=u0.w;
        b[4]=u1.x; b[5]=u1.y; b[6]=u1.z; b[7]=u1.w;
#pragma unroll
        for (int r = 0; r < 8; ++r)
#pragma unroll
            for (int c = 0; c < 8; ++c)
                acc[r][c] = fmaf(a[r], b[c], acc[r][c]);
    }

    // epilogue: dist, exp, per-thread stats
    float rsum[8], csum[8];
    unsigned long long rpack[8], cpack[8];
#pragma unroll
    for (int r = 0; r < 8; ++r) { rsum[r] = 0.f; rpack[r] = 0ull; }
#pragma unroll
    for (int c = 0; c < 8; ++c) { csum[c] = 0.f; cpack[c] = 0ull; }

#pragma unroll
    for (int r = 0; r < 8; ++r) {
        float xq = sxq[i0 + r];
        unsigned inv_i = ~(unsigned)(ibase + i0 + r);
#pragma unroll
        for (int c = 0; c < 8; ++c) {
            float sq = xq + syq[j0 + c] - 2.f * acc[r][c];
            float dist = sqrtf(fmaxf(sq, 0.f));
            float Dm = 2.f - dist;
            float p = __expf(-dist);
            rsum[r] += p;
            csum[c] += p;
            unsigned long long key = ((unsigned long long)fkey(Dm)) << 32;
            unsigned long long pr = key | (unsigned)~(unsigned)(jbase + j0 + c);
            unsigned long long pc = key | inv_i;
            if (pr > rpack[r]) rpack[r] = pr;
            if (pc > cpack[c]) cpack[c] = pc;
        }
    }

    // row reduce across tx (lanes within 16-lane half-warp groups)
#pragma unroll
    for (int r = 0; r < 8; ++r) {
#pragma unroll
        for (int off = 8; off >= 1; off >>= 1) {
            rsum[r] += __shfl_xor_sync(0xFFFFFFFFu, rsum[r], off);
            unsigned long long o = __shfl_xor_sync(0xFFFFFFFFu, rpack[r], off);
            if (o > rpack[r]) rpack[r] = o;
        }
    }
    if (tx == 0) {
#pragma unroll
        for (int r = 0; r < 8; ++r) {
            atomicAdd(&g_rowsum[ibase + i0 + r], rsum[r]);
            atomicMax(&g_rowmaxp[ibase + i0 + r], rpack[r]);
        }
    }

    // col reduce across ty via smem
    if (ty == 0) {
#pragma unroll
        for (int c = 0; c < 8; ++c) { scsum[j0 + c] = csum[c]; scmax[j0 + c] = cpack[c]; }
    }
    __syncthreads();
    if (ty != 0) {
#pragma unroll
        for (int c = 0; c < 8; ++c) {
            atomicAdd(&scsum[j0 + c], csum[c]);
            atomicMax(&scmax[j0 + c], cpack[c]);
        }
    }
    __syncthreads();
    if (ty == 0) {
#pragma unroll
        for (int c = 0; c < 8; ++c) {
            atomicAdd(&g_colsum[jbase + j0 + c], scsum[j0 + c]);
            atomicMax(&g_colmaxp[jbase + j0 + c], scmax[j0 + c]);
        }
    }
}

// ---------------- finalize 1: per-row/col lse, choice, lp ----------------
__global__ void finalize1_kernel() {
    int t = blockIdx.x * blockDim.x + threadIdx.x;
    if (t >= NN) return;
    {
        unsigned long long p = g_rowmaxp[t];
        float Dmax = unfkey((unsigned)(p >> 32));
        int idx = (int)(~(unsigned)(p & 0xFFFFFFFFull));
        g_choice_rows[t] = idx;
        g_lp_rows[t] = Dmax - (2.f + logf(g_rowsum[t]));
    }
    {
        unsigned long long p = g_colmaxp[t];
        float Dmax = unfkey((unsigned)(p >> 32));
        int idx = (int)(~(unsigned)(p & 0xFFFFFFFFull));
        g_choice_cols[t] = idx;
        g_lp_cols[t] = Dmax - (2.f + logf(g_colsum[t]));
    }
}

// ---------------- finalize 2: mutual match + outputs ----------------
// out layout (float32): [0:M) log_probs, [M:3M) dmatches (cc, j) pairs, [3M:4M) mutual
__global__ void finalize2_kernel(float* __restrict__ out) {
    int j = blockIdx.x * blockDim.x + threadIdx.x;
    if (j >= MM) return;
    int cc = g_choice_cols[j];
    bool mut = (g_choice_rows[cc] == j);
    out[j] = mut ? (g_lp_rows[cc] + g_lp_cols[j]) : 0.f;
    out[MM + 2 * j]     = (float)cc;
    out[MM + 2 * j + 1] = (float)j;
    out[3 * MM + j] = mut ? 1.f : 0.f;
}

extern "C" void kernel_launch(void* const* d_in, const int* in_sizes, int n_in,
                              void* d_out, int out_size) {
    const float* x = (const float*)d_in[0];
    const float* y = (const float*)d_in[1];
    float* out = (float*)d_out;

    init_kernel<<<(NN + 255) / 256, 256>>>();
    sqnorm_kernel<<<(2 * NN + 255) / 256, 256>>>(x, y);

    static int smem_set = 0;
    if (!smem_set) {
        cudaFuncSetAttribute(matcher_main_kernel,
                             cudaFuncAttributeMaxDynamicSharedMemorySize,
                             SMEM_TOTAL);
        smem_set = 1;
    }
    dim3 grid(NTILE, NTILE);
    matcher_main_kernel<<<grid, 256, SMEM_TOTAL>>>(x, y);

    finalize1_kernel<<<(NN + 255) / 256, 256>>>();
    finalize2_kernel<<<(MM + 255) / 256, 256>>>(out);
}

// round 3
// speedup vs baseline: 1.0004x; 1.0004x over previous
#include <cuda_runtime.h>
#include <cuda_bf16.h>
#include <stdint.h>

// Problem constants
#define NN 8192
#define MM 8192
#define DD 64
#define TILE 128
#define NTILE (NN / TILE)   // 64

// ---------------- device scratch (no allocations allowed) ----------------
__device__ float g_xsq[NN];
__device__ float g_ysq[MM];
__device__ float g_rowsum[NN];
__device__ float g_colsum[MM];
__device__ unsigned long long g_rowmaxp[NN];
__device__ unsigned long long g_colmaxp[MM];
__device__ float g_lp_rows[NN];
__device__ float g_lp_cols[MM];
__device__ int   g_choice_rows[NN];
__device__ int   g_choice_cols[MM];

// Orderable key for float: larger float -> larger uint
__device__ __forceinline__ unsigned fkey(float f) {
    unsigned u = __float_as_uint(f);
    return u ^ ((unsigned)(((int)u) >> 31) | 0x80000000u);
}
__device__ __forceinline__ float unfkey(unsigned k) {
    unsigned u = (k & 0x80000000u) ? (k ^ 0x80000000u) : ~k;
    return __uint_as_float(u);
}

// ---------------- init ----------------
__global__ void init_kernel() {
    int t = blockIdx.x * blockDim.x + threadIdx.x;
    if (t < NN) {
        g_rowsum[t] = 0.f;
        g_colsum[t] = 0.f;
        g_rowmaxp[t] = 0ull;
        g_colmaxp[t] = 0ull;
    }
}

// ---------------- squared norms ----------------
__global__ void sqnorm_kernel(const float* __restrict__ x,
                              const float* __restrict__ y) {
    int t = blockIdx.x * blockDim.x + threadIdx.x;
    if (t >= 2 * NN) return;
    const float* base = (t < NN) ? (x + (size_t)t * DD)
                                 : (y + (size_t)(t - NN) * DD);
    float s = 0.f;
#pragma unroll
    for (int k = 0; k < DD / 4; ++k) {
        float4 v = *(const float4*)(base + 4 * k);
        s += v.x * v.x + v.y * v.y + v.z * v.z + v.w * v.w;
    }
    if (t < NN) g_xsq[t] = s; else g_ysq[t - NN] = s;
}

// ---------------- main fused distance + softmax-stats kernel ----------------
// Tile 128x128, 256 threads, 8x8 per-thread microtile, K=64 in one shot.
// Dynamic smem layout:
//   float xT[64][132]  (x tile transposed, padded)
//   float yT[64][132]
//   float sxq[128], syq[128]
//   float scsum[128]; unsigned long long scmax[128]
#define XT_STRIDE 132
#define SMEM_XT 0
#define SMEM_YT (SMEM_XT + 64 * XT_STRIDE * 4)
#define SMEM_SXQ (SMEM_YT + 64 * XT_STRIDE * 4)
#define SMEM_SYQ (SMEM_SXQ + 128 * 4)
#define SMEM_CSUM (SMEM_SYQ + 128 * 4)
#define SMEM_CMAX ((SMEM_CSUM + 128 * 4 + 15) & ~15)
#define SMEM_TOTAL (SMEM_CMAX + 128 * 8)

__global__ void __launch_bounds__(256, 2)
matcher_main_kernel(const float* __restrict__ x, const float* __restrict__ y) {
    extern __shared__ char smem[];
    float* xT = (float*)(smem + SMEM_XT);
    float* yT = (float*)(smem + SMEM_YT);
    float* sxq = (float*)(smem + SMEM_SXQ);
    float* syq = (float*)(smem + SMEM_SYQ);
    float* scsum = (float*)(smem + SMEM_CSUM);
    unsigned long long* scmax = (unsigned long long*)(smem + SMEM_CMAX);

    const int tid = threadIdx.x;
    const int tx = tid & 15;          // 0..15 -> column group
    const int ty = tid >> 4;          // 0..15 -> row group
    const int i0 = ty * 8;
    const int j0 = tx * 8;
    const int ibase = blockIdx.y * TILE;
    const int jbase = blockIdx.x * TILE;

    // load tiles, transposed into smem
#pragma unroll
    for (int k = tid; k < TILE * (DD / 4); k += 256) {  // 2048 float4
        int r = k >> 4;
        int c4 = k & 15;
        float4 vx = *(const float4*)(x + (size_t)(ibase + r) * DD + c4 * 4);
        float4 vy = *(const float4*)(y + (size_t)(jbase + r) * DD + c4 * 4);
        int d = c4 * 4;
        xT[(d + 0) * XT_STRIDE + r] = vx.x;
        xT[(d + 1) * XT_STRIDE + r] = vx.y;
        xT[(d + 2) * XT_STRIDE + r] = vx.z;
        xT[(d + 3) * XT_STRIDE + r] = vx.w;
        yT[(d + 0) * XT_STRIDE + r] = vy.x;
        yT[(d + 1) * XT_STRIDE + r] = vy.y;
        yT[(d + 2) * XT_STRIDE + r] = vy.z;
        yT[(d + 3) * XT_STRIDE + r] = vy.w;
    }
    if (tid < 128) sxq[tid] = g_xsq[ibase + tid];
    else           syq[tid - 128] = g_ysq[jbase + tid - 128];
    __syncthreads();

    float acc[8][8];
#pragma unroll
    for (int r = 0; r < 8; ++r)
#pragma unroll
        for (int c = 0; c < 8; ++c) acc[r][c] = 0.f;

#pragma unroll 8
    for (int d = 0; d < DD; ++d) {
        float a[8], b[8];
        float4 t0 = *(const float4*)&xT[d * XT_STRIDE + i0];
        float4 t1 = *(const float4*)&xT[d * XT_STRIDE + i0 + 4];
        float4 u0 = *(const float4*)&yT[d * XT_STRIDE + j0];
        float4 u1 = *(const float4*)&yT[d * XT_STRIDE + j0 + 4];
        a[0]=t0.x; a[1]=t0.y; a[2]=t0.z; a[3]=t0.w;
        a[4]=t1.x; a[5]=t1.y; a[6]=t1.z; a[7]=t1.w;
        b[0]=u0.x; b[1]=u0.y; b[2]=u0.z; b[3]=u0.w;
        b[4]=u1.x; b[5]=u1.y; b[6]=u1.z; b[7]=u1.w;
#pragma unroll
        for (int r = 0; r < 8; ++r)
#pragma unroll
            for (int c = 0; c < 8; ++c)
                acc[r][c] = fmaf(a[r], b[c], acc[r][c]);
    }

    // epilogue: dist, exp, per-thread stats
    float rsum[8], csum[8];
    unsigned long long rpack[8], cpack[8];
#pragma unroll
    for (int r = 0; r < 8; ++r) { rsum[r] = 0.f; rpack[r] = 0ull; }
#pragma unroll
    for (int c = 0; c < 8; ++c) { csum[c] = 0.f; cpack[c] = 0ull; }

#pragma unroll
    for (int r = 0; r < 8; ++r) {
        float xq = sxq[i0 + r];
        unsigned inv_i = ~(unsigned)(ibase + i0 + r);
#pragma unroll
        for (int c = 0; c < 8; ++c) {
            float sq = xq + syq[j0 + c] - 2.f * acc[r][c];
            float dist = sqrtf(fmaxf(sq, 0.f));
            float Dm = 2.f - dist;
            float p = __expf(-dist);
            rsum[r] += p;
            csum[c] += p;
            unsigned long long key = ((unsigned long long)fkey(Dm)) << 32;
            unsigned long long pr = key | (unsigned)~(unsigned)(jbase + j0 + c);
            unsigned long long pc = key | inv_i;
            if (pr > rpack[r]) rpack[r] = pr;
            if (pc > cpack[c]) cpack[c] = pc;
        }
    }

    // row reduce across tx (lanes within 16-lane half-warp groups)
#pragma unroll
    for (int r = 0; r < 8; ++r) {
#pragma unroll
        for (int off = 8; off >= 1; off >>= 1) {
            rsum[r] += __shfl_xor_sync(0xFFFFFFFFu, rsum[r], off);
            unsigned long long o = __shfl_xor_sync(0xFFFFFFFFu, rpack[r], off);
            if (o > rpack[r]) rpack[r] = o;
        }
    }
    if (tx == 0) {
#pragma unroll
        for (int r = 0; r < 8; ++r) {
            atomicAdd(&g_rowsum[ibase + i0 + r], rsum[r]);
            atomicMax(&g_rowmaxp[ibase + i0 + r], rpack[r]);
        }
    }

    // col reduce across ty via smem
    if (ty == 0) {
#pragma unroll
        for (int c = 0; c < 8; ++c) { scsum[j0 + c] = csum[c]; scmax[j0 + c] = cpack[c]; }
    }
    __syncthreads();
    if (ty != 0) {
#pragma unroll
        for (int c = 0; c < 8; ++c) {
            atomicAdd(&scsum[j0 + c], csum[c]);
            atomicMax(&scmax[j0 + c], cpack[c]);
        }
    }
    __syncthreads();
    if (ty == 0) {
#pragma unroll
        for (int c = 0; c < 8; ++c) {
            atomicAdd(&g_colsum[jbase + j0 + c], scsum[j0 + c]);
            atomicMax(&g_colmaxp[jbase + j0 + c], scmax[j0 + c]);
        }
    }
}

// ---------------- finalize 1: per-row/col lse, choice, lp ----------------
__global__ void finalize1_kernel() {
    int t = blockIdx.x * blockDim.x + threadIdx.x;
    if (t >= NN) return;
    {
        unsigned long long p = g_rowmaxp[t];
        float Dmax = unfkey((unsigned)(p >> 32));
        int idx = (int)(~(unsigned)(p & 0xFFFFFFFFull));
        g_choice_rows[t] = idx;
        g_lp_rows[t] = Dmax - (2.f + logf(g_rowsum[t]));
    }
    {
        unsigned long long p = g_colmaxp[t];
        float Dmax = unfkey((unsigned)(p >> 32));
        int idx = (int)(~(unsigned)(p & 0xFFFFFFFFull));
        g_choice_cols[t] = idx;
        g_lp_cols[t] = Dmax - (2.f + logf(g_colsum[t]));
    }
}

// ---------------- finalize 2: mutual match + outputs ----------------
// out layout (float32): [0:M) log_probs, [M:3M) dmatches (cc, j) pairs, [3M:4M) mutual
__global__ void finalize2_kernel(float* __restrict__ out) {
    int j = blockIdx.x * blockDim.x + threadIdx.x;
    if (j >= MM) return;
    int cc = g_choice_cols[j];
    bool mut = (g_choice_rows[cc] == j);
    out[j] = mut ? (g_lp_rows[cc] + g_lp_cols[j]) : 0.f;
    out[MM + 2 * j]     = (float)cc;
    out[MM + 2 * j + 1] = (float)j;
    out[3 * MM + j] = mut ? 1.f : 0.f;
}

extern "C" void kernel_launch(void* const* d_in, const int* in_sizes, int n_in,
                              void* d_out, int out_size) {
    const float* x = (const float*)d_in[0];
    const float* y = (const float*)d_in[1];
    float* out = (float*)d_out;

    init_kernel<<<(NN + 255) / 256, 256>>>();
    sqnorm_kernel<<<(2 * NN + 255) / 256, 256>>>(x, y);

    static int smem_set = 0;
    if (!smem_set) {
        cudaFuncSetAttribute(matcher_main_kernel,
                             cudaFuncAttributeMaxDynamicSharedMemorySize,
                             SMEM_TOTAL);
        smem_set = 1;
    }
    dim3 grid(NTILE, NTILE);
    matcher_main_kernel<<<grid, 256, SMEM_TOTAL>>>(x, y);

    finalize1_kernel<<<(NN + 255) / 256, 256>>>();
    finalize2_kernel<<<(MM + 255) / 256, 256>>>(out);
}

// round 4
// speedup vs baseline: 1.0036x; 1.0032x over previous
#include <cuda_runtime.h>
#include <cuda_bf16.h>
#include <stdint.h>

// Problem constants
#define NN 8192
#define MM 8192
#define DD 64
#define TILE 128
#define NTILE (NN / TILE)   // 64

// ---------------- device scratch (no allocations allowed) ----------------
__device__ float g_xsq[NN];
__device__ float g_ysq[MM];
__device__ float g_rowsum[NN];
__device__ float g_colsum[MM];
__device__ unsigned long long g_rowmaxp[NN];
__device__ unsigned long long g_colmaxp[MM];
__device__ float g_lp_rows[NN];
__device__ float g_lp_cols[MM];
__device__ int   g_choice_rows[NN];
__device__ int   g_choice_cols[MM];

// Orderable key for float: larger float -> larger uint
__device__ __forceinline__ unsigned fkey(float f) {
    unsigned u = __float_as_uint(f);
    return u ^ ((unsigned)(((int)u) >> 31) | 0x80000000u);
}
__device__ __forceinline__ float unfkey(unsigned k) {
    unsigned u = (k & 0x80000000u) ? (k ^ 0x80000000u) : ~k;
    return __uint_as_float(u);
}

// ---------------- init ----------------
__global__ void init_kernel() {
    int t = blockIdx.x * blockDim.x + threadIdx.x;
    if (t < NN) {
        g_rowsum[t] = 0.f;
        g_colsum[t] = 0.f;
        g_rowmaxp[t] = 0ull;
        g_colmaxp[t] = 0ull;
    }
}

// ---------------- squared norms ----------------
__global__ void sqnorm_kernel(const float* __restrict__ x,
                              const float* __restrict__ y) {
    int t = blockIdx.x * blockDim.x + threadIdx.x;
    if (t >= 2 * NN) return;
    const float* base = (t < NN) ? (x + (size_t)t * DD)
                                 : (y + (size_t)(t - NN) * DD);
    float s = 0.f;
#pragma unroll
    for (int k = 0; k < DD / 4; ++k) {
        float4 v = *(const float4*)(base + 4 * k);
        s += v.x * v.x + v.y * v.y + v.z * v.z + v.w * v.w;
    }
    if (t < NN) g_xsq[t] = s; else g_ysq[t - NN] = s;
}

// ---------------- main fused distance + softmax-stats kernel ----------------
// Tile 128x128, 256 threads, 8x8 per-thread microtile, K=64 in one shot.
// Dynamic smem layout:
//   float xT[64][132]  (x tile transposed, padded)
//   float yT[64][132]
//   float sxq[128], syq[128]
//   float scsum[128]; unsigned long long scmax[128]
#define XT_STRIDE 132
#define SMEM_XT 0
#define SMEM_YT (SMEM_XT + 64 * XT_STRIDE * 4)
#define SMEM_SXQ (SMEM_YT + 64 * XT_STRIDE * 4)
#define SMEM_SYQ (SMEM_SXQ + 128 * 4)
#define SMEM_CSUM (SMEM_SYQ + 128 * 4)
#define SMEM_CMAX ((SMEM_CSUM + 128 * 4 + 15) & ~15)
#define SMEM_TOTAL (SMEM_CMAX + 128 * 8)

__global__ void __launch_bounds__(256, 2)
matcher_main_kernel(const float* __restrict__ x, const float* __restrict__ y) {
    extern __shared__ char smem[];
    float* xT = (float*)(smem + SMEM_XT);
    float* yT = (float*)(smem + SMEM_YT);
    float* sxq = (float*)(smem + SMEM_SXQ);
    float* syq = (float*)(smem + SMEM_SYQ);
    float* scsum = (float*)(smem + SMEM_CSUM);
    unsigned long long* scmax = (unsigned long long*)(smem + SMEM_CMAX);

    const int tid = threadIdx.x;
    const int tx = tid & 15;          // 0..15 -> column group
    const int ty = tid >> 4;          // 0..15 -> row group
    const int i0 = ty * 8;
    const int j0 = tx * 8;
    const int ibase = blockIdx.y * TILE;
    const int jbase = blockIdx.x * TILE;

    // load tiles, transposed into smem
#pragma unroll
    for (int k = tid; k < TILE * (DD / 4); k += 256) {  // 2048 float4
        int r = k >> 4;
        int c4 = k & 15;
        float4 vx = *(const float4*)(x + (size_t)(ibase + r) * DD + c4 * 4);
        float4 vy = *(const float4*)(y + (size_t)(jbase + r) * DD + c4 * 4);
        int d = c4 * 4;
        xT[(d + 0) * XT_STRIDE + r] = vx.x;
        xT[(d + 1) * XT_STRIDE + r] = vx.y;
        xT[(d + 2) * XT_STRIDE + r] = vx.z;
        xT[(d + 3) * XT_STRIDE + r] = vx.w;
        yT[(d + 0) * XT_STRIDE + r] = vy.x;
        yT[(d + 1) * XT_STRIDE + r] = vy.y;
        yT[(d + 2) * XT_STRIDE + r] = vy.z;
        yT[(d + 3) * XT_STRIDE + r] = vy.w;
    }
    if (tid < 128) sxq[tid] = g_xsq[ibase + tid];
    else           syq[tid - 128] = g_ysq[jbase + tid - 128];
    __syncthreads();

    float acc[8][8];
#pragma unroll
    for (int r = 0; r < 8; ++r)
#pragma unroll
        for (int c = 0; c < 8; ++c) acc[r][c] = 0.f;

#pragma unroll 8
    for (int d = 0; d < DD; ++d) {
        float a[8], b[8];
        float4 t0 = *(const float4*)&xT[d * XT_STRIDE + i0];
        float4 t1 = *(const float4*)&xT[d * XT_STRIDE + i0 + 4];
        float4 u0 = *(const float4*)&yT[d * XT_STRIDE + j0];
        float4 u1 = *(const float4*)&yT[d * XT_STRIDE + j0 + 4];
        a[0]=t0.x; a[1]=t0.y; a[2]=t0.z; a[3]=t0.w;
        a[4]=t1.x; a[5]=t1.y; a[6]=t1.z; a[7]=t1.w;
        b[0]=u0.x; b[1]=u0.y; b[2]=u0.z; b[3]=u0.w;
        b[4]=u1.x; b[5]=u1.y; b[6]=u1.z; b[7]=u1.w;
#pragma unroll
        for (int r = 0; r < 8; ++r)
#pragma unroll
            for (int c = 0; c < 8; ++c)
                acc[r][c] = fmaf(a[r], b[c], acc[r][c]);
    }

    // epilogue: dist, exp, per-thread stats
    float rsum[8], csum[8];
    unsigned long long rpack[8], cpack[8];
#pragma unroll
    for (int r = 0; r < 8; ++r) { rsum[r] = 0.f; rpack[r] = 0ull; }
#pragma unroll
    for (int c = 0; c < 8; ++c) { csum[c] = 0.f; cpack[c] = 0ull; }

#pragma unroll
    for (int r = 0; r < 8; ++r) {
        float xq = sxq[i0 + r];
        unsigned inv_i = ~(unsigned)(ibase + i0 + r);
#pragma unroll
        for (int c = 0; c < 8; ++c) {
            float sq = xq + syq[j0 + c] - 2.f * acc[r][c];
            float dist = sqrtf(fmaxf(sq, 0.f));
            float Dm = 2.f - dist;
            float p = __expf(-dist);
            rsum[r] += p;
            csum[c] += p;
            unsigned long long key = ((unsigned long long)fkey(Dm)) << 32;
            unsigned long long pr = key | (unsigned)~(unsigned)(jbase + j0 + c);
            unsigned long long pc = key | inv_i;
            if (pr > rpack[r]) rpack[r] = pr;
            if (pc > cpack[c]) cpack[c] = pc;
        }
    }

    // row reduce across tx (lanes within 16-lane half-warp groups)
#pragma unroll
    for (int r = 0; r < 8; ++r) {
#pragma unroll
        for (int off = 8; off >= 1; off >>= 1) {
            rsum[r] += __shfl_xor_sync(0xFFFFFFFFu, rsum[r], off);
            unsigned long long o = __shfl_xor_sync(0xFFFFFFFFu, rpack[r], off);
            if (o > rpack[r]) rpack[r] = o;
        }
    }
    if (tx == 0) {
#pragma unroll
        for (int r = 0; r < 8; ++r) {
            atomicAdd(&g_rowsum[ibase + i0 + r], rsum[r]);
            atomicMax(&g_rowmaxp[ibase + i0 + r], rpack[r]);
        }
    }

    // col reduce across ty via smem
    if (ty == 0) {
#pragma unroll
        for (int c = 0; c < 8; ++c) { scsum[j0 + c] = csum[c]; scmax[j0 + c] = cpack[c]; }
    }
    __syncthreads();
    if (ty != 0) {
#pragma unroll
        for (int c = 0; c < 8; ++c) {
            atomicAdd(&scsum[j0 + c], csum[c]);
            atomicMax(&scmax[j0 + c], cpack[c]);
        }
    }
    __syncthreads();
    if (ty == 0) {
#pragma unroll
        for (int c = 0; c < 8; ++c) {
            atomicAdd(&g_colsum[jbase + j0 + c], scsum[j0 + c]);
            atomicMax(&g_colmaxp[jbase + j0 + c], scmax[j0 + c]);
        }
    }
}

// ---------------- finalize 1: per-row/col lse, choice, lp ----------------
__global__ void finalize1_kernel() {
    int t = blockIdx.x * blockDim.x + threadIdx.x;
    if (t >= NN) return;
    {
        unsigned long long p = g_rowmaxp[t];
        float Dmax = unfkey((unsigned)(p >> 32));
        int idx = (int)(~(unsigned)(p & 0xFFFFFFFFull));
        g_choice_rows[t] = idx;
        g_lp_rows[t] = Dmax - (2.f + logf(g_rowsum[t]));
    }
    {
        unsigned long long p = g_colmaxp[t];
        float Dmax = unfkey((unsigned)(p >> 32));
        int idx = (int)(~(unsigned)(p & 0xFFFFFFFFull));
        g_choice_cols[t] = idx;
        g_lp_cols[t] = Dmax - (2.f + logf(g_colsum[t]));
    }
}

// ---------------- finalize 2: mutual match + outputs ----------------
// out layout (float32): [0:M) log_probs, [M:3M) dmatches (cc, j) pairs, [3M:4M) mutual
__global__ void finalize2_kernel(float* __restrict__ out) {
    int j = blockIdx.x * blockDim.x + threadIdx.x;
    if (j >= MM) return;
    int cc = g_choice_cols[j];
    bool mut = (g_choice_rows[cc] == j);
    out[j] = mut ? (g_lp_rows[cc] + g_lp_cols[j]) : 0.f;
    out[MM + 2 * j]     = (float)cc;
    out[MM + 2 * j + 1] = (float)j;
    out[3 * MM + j] = mut ? 1.f : 0.f;
}

extern "C" void kernel_launch(void* const* d_in, const int* in_sizes, int n_in,
                              void* d_out, int out_size) {
    const float* x = (const float*)d_in[0];
    const float* y = (const float*)d_in[1];
    float* out = (float*)d_out;

    init_kernel<<<(NN + 255) / 256, 256>>>();
    sqnorm_kernel<<<(2 * NN + 255) / 256, 256>>>(x, y);

    static int smem_set = 0;
    if (!smem_set) {
        cudaFuncSetAttribute(matcher_main_kernel,
                             cudaFuncAttributeMaxDynamicSharedMemorySize,
                             SMEM_TOTAL);
        smem_set = 1;
    }
    dim3 grid(NTILE, NTILE);
    matcher_main_kernel<<<grid, 256, SMEM_TOTAL>>>(x, y);

    finalize1_kernel<<<(NN + 255) / 256, 256>>>();
    finalize2_kernel<<<(MM + 255) / 256, 256>>>(out);
}